// round 10
// baseline (speedup 1.0000x reference)
#include <cuda_runtime.h>
#include <cstdint>

// Conv1dLocal: out[b,o,s] = sum_{i,k} x[b,i,s+k] * w[o,i,s,k]
// B=32, IC=OC=64, S=512, KW=7, STRIDE=1, L=518.
// fp32x2 packed FMAs, b-pairs in lanes. Thread: (s, 4 o) x 8 b-pairs.
// Block: 16 s x 32 o x 16 b x 8 i, 128 threads. Grid 32 x 2 x 16 = 1024.
// Weights: warp-private smem tiles (8o x 16s x 7k), rows PADDED to 116 floats
// so the two warp-halves hit disjoint bank sets (conflict-free LDS.32),
// double-buffered cp.async (dense LDG.128).
// 8-way i-split partials combined via float atomicAdd into zeroed output.

#define B_   32
#define IC_  64
#define OC_  64
#define S_   512
#define KW_  7
#define L_   518

#define S_TILE        16
#define O_PER_THREAD  4
#define BP_PER_BLOCK  8
#define I_PER_BLOCK   8
#define POS           (S_TILE + KW_ - 1)       // 22
#define THREADS       128
#define XS_ELEMS      (I_PER_BLOCK * BP_PER_BLOCK * POS)  // 1408 = 11*128

#define I_STRIDE      (S_ * KW_)               // 3584 floats
#define W_ROW_F       116                      // padded per-o row (floats); 116%8==4 -> h-stride 464 == 16 mod 32
#define W_WARP_BYTES  (8 * W_ROW_F * 4)        // 3712 B per warp tile
#define W_BUF_BYTES   (4 * W_WARP_BYTES)       // 14848 per buffer (4 warps)
#define XS_BYTES      (XS_ELEMS * 8)           // 11264
#define SMEM_TOTAL    (XS_BYTES + 2 * W_BUF_BYTES)  // 40960

typedef unsigned long long ull;

__device__ __forceinline__ ull pack2(float w) {
    unsigned u = __float_as_uint(w);
    ull r;
    asm("mov.b64 %0, {%1, %1};" : "=l"(r) : "r"(u));
    return r;
}

__device__ __forceinline__ void ffma2(ull &d, ull a, ull b) {
    asm("fma.rn.f32x2 %0, %1, %2, %0;" : "+l"(d) : "l"(a), "l"(b));
}

__device__ __forceinline__ void cp16(unsigned dst, const void* src) {
    asm volatile("cp.async.cg.shared.global [%0], [%1], 16;" :: "r"(dst), "l"(src));
}

__global__ __launch_bounds__(THREADS, 5)
void conv1d_local_kernel(const float* __restrict__ x,
                         const float* __restrict__ w,
                         float* __restrict__ out)
{
    extern __shared__ char smem[];
    // [0, 11264): x tile, float2 xs[(i_l*BP + bp)*POS + pos] = {x[2bp], x[2bp+1]}
    // [11264, 40960): weight tiles [buf][warp][8o x 116f padded rows]
    float2* xs = reinterpret_cast<float2*>(smem);
    char*   ws = smem + XS_BYTES;

    const int tid     = threadIdx.x;
    const int lane    = tid & 31;
    const int warp    = tid >> 5;
    const int s_local = tid & (S_TILE - 1);
    const int og      = tid >> 4;                  // 0..7
    const int h       = og & 1;                    // half within warp
    const int s0      = blockIdx.x * S_TILE;
    const int o_base  = blockIdx.y * 32 + og * O_PER_THREAD;
    const int b_blk   = blockIdx.z & 1;
    const int i_blk   = blockIdx.z >> 1;           // 0..7
    const int b0      = b_blk * (2 * BP_PER_BLOCK);
    const int i0      = i_blk * I_PER_BLOCK;
    const int s       = s0 + s_local;

    // ---- cp.async setup: lane's c-th chunk -> idx = c*32+lane in [0,224)
    // o_idx = idx/28, f4 = idx%28; per o, 112 contiguous floats (28 f4) at
    // w[((o*IC+i)*S + s0)*KW]; smem row padded to 116 floats.
    const unsigned ws_base =
        (unsigned)__cvta_generic_to_shared(ws + warp * W_WARP_BYTES);
    const float* srcp[7];
    unsigned dsto[7];
    #pragma unroll
    for (int c = 0; c < 7; ++c) {
        int idx   = c * 32 + lane;       // 0..223
        int o_idx = idx / 28;
        int f4    = idx - o_idx * 28;
        int o     = blockIdx.y * 32 + warp * 8 + o_idx;
        srcp[c] = w + (((size_t)o * IC_ + i0) * S_ + s0) * KW_ + f4 * 4;
        dsto[c] = (unsigned)(o_idx * (W_ROW_F * 4) + f4 * 16);
    }

    // prefetch weights for i=0 into buf 0
    #pragma unroll
    for (int c = 0; c < 7; ++c)
        cp16(ws_base + dsto[c], srcp[c]);
    asm volatile("cp.async.commit_group;");

    // ---- cooperative x tile load: 8 i x 8 bp x 22 pos
    #pragma unroll
    for (int it = 0; it < XS_ELEMS / THREADS; ++it) {
        int t   = it * THREADS + tid;
        int i_l = t / (BP_PER_BLOCK * POS);
        int r   = t - i_l * (BP_PER_BLOCK * POS);
        int bp  = r / POS;
        int pos = r - bp * POS;
        int b   = b0 + 2 * bp;
        const float* xp = x + ((size_t)b * IC_ + (i0 + i_l)) * L_ + s0 + pos;
        xs[t] = make_float2(xp[0], xp[(size_t)IC_ * L_]);
    }

    ull acc[O_PER_THREAD][BP_PER_BLOCK];
    #pragma unroll
    for (int j = 0; j < O_PER_THREAD; j++)
        #pragma unroll
        for (int bp = 0; bp < BP_PER_BLOCK; bp++)
            acc[j][bp] = 0ull;

    __syncthreads();   // x tile ready

    // consume: thread reads wsf[h*464 + j*116 + s_local*7 + k]
    // banks: {7s+k} (h=0) and {7s+k+16} (h=1) are disjoint mod 32 -> conflict-free
    const float* wsf0 = reinterpret_cast<const float*>(ws + warp * W_WARP_BYTES);
    const float* wsf1 = reinterpret_cast<const float*>(ws + W_BUF_BYTES + warp * W_WARP_BYTES);
    const int toff = h * (4 * W_ROW_F) + s_local * 7;

    #pragma unroll 2
    for (int i_l = 0; i_l < I_PER_BLOCK; ++i_l) {
        if (i_l + 1 < I_PER_BLOCK) {
            unsigned db = ws_base + (unsigned)(((i_l + 1) & 1) * W_BUF_BYTES);
            #pragma unroll
            for (int c = 0; c < 7; ++c)
                cp16(db + dsto[c], srcp[c] + (size_t)(i_l + 1) * I_STRIDE);
            asm volatile("cp.async.commit_group;");
            asm volatile("cp.async.wait_group 1;");
        } else {
            asm volatile("cp.async.wait_group 0;");
        }
        __syncwarp();

        const float* wsf = (i_l & 1) ? wsf1 : wsf0;
        const float2* xb = xs + i_l * (BP_PER_BLOCK * POS) + s_local;

        #pragma unroll
        for (int k = 0; k < KW_; ++k) {
            ull w2[O_PER_THREAD];
            #pragma unroll
            for (int j = 0; j < O_PER_THREAD; ++j)
                w2[j] = pack2(wsf[toff + j * W_ROW_F + k]);
            #pragma unroll
            for (int bp = 0; bp < BP_PER_BLOCK; ++bp) {
                ull x2 = *reinterpret_cast<const ull*>(&xb[bp * POS + k]);
                #pragma unroll
                for (int j = 0; j < O_PER_THREAD; ++j)
                    ffma2(acc[j][bp], x2, w2[j]);
            }
        }
        __syncwarp();  // all lanes done with buffer before next overwrite
    }

    // accumulate partials (8 i-split blocks per output; out pre-zeroed)
    #pragma unroll
    for (int j = 0; j < O_PER_THREAD; ++j) {
        #pragma unroll
        for (int bp = 0; bp < BP_PER_BLOCK; ++bp) {
            float lo = __uint_as_float((unsigned)(acc[j][bp] & 0xffffffffull));
            float hi = __uint_as_float((unsigned)(acc[j][bp] >> 32));
            int b = b0 + 2 * bp;
            atomicAdd(&out[((size_t)b * OC_ + (o_base + j)) * S_ + s], lo);
            atomicAdd(&out[((size_t)(b + 1) * OC_ + (o_base + j)) * S_ + s], hi);
        }
    }
}

extern "C" void kernel_launch(void* const* d_in, const int* in_sizes, int n_in,
                              void* d_out, int out_size)
{
    const float* x = (const float*)d_in[0];
    const float* w = (const float*)d_in[1];
    float* out = (float*)d_out;

    cudaFuncSetAttribute(conv1d_local_kernel,
                         cudaFuncAttributeMaxDynamicSharedMemorySize, SMEM_TOTAL);

    cudaMemsetAsync(out, 0, (size_t)out_size * sizeof(float), 0);

    dim3 grid(S_ / S_TILE, OC_ / 32,
              (B_ / (2 * BP_PER_BLOCK)) * (IC_ / I_PER_BLOCK)); // 32,2,16
    conv1d_local_kernel<<<grid, THREADS, SMEM_TOTAL>>>(x, w, out);
}

// round 11
// speedup vs baseline: 1.2719x; 1.2719x over previous
#include <cuda_runtime.h>
#include <cstdint>

// Conv1dLocal: out[b,o,s] = sum_{i,k} x[b,i,s+k] * w[o,i,s,k]
// B=32, IC=OC=64, S=512, KW=7, STRIDE=1, L=518.
// fp32x2 packed FMAs, b-pairs in lanes. Thread: (s, 4 o) x 8 b-pairs.
// Block: 16 s x 32 o x 16 b x 16 i, 128 threads. Grid 32 x 2 x 8 = 512.
// Weights: warp-private smem tiles (8o x 16s x 7k), rows PADDED to 116 floats
// so the two warp-halves hit disjoint bank sets (conflict-free LDS.32),
// double-buffered cp.async (dense LDG.128).
// (Round-10 lesson: i-split 8 doubled per-block fixed costs -> revert to 16.)
// 4-way i-split partials combined via float atomicAdd into zeroed output.

#define B_   32
#define IC_  64
#define OC_  64
#define S_   512
#define KW_  7
#define L_   518

#define S_TILE        16
#define O_PER_THREAD  4
#define BP_PER_BLOCK  8
#define I_PER_BLOCK   16
#define POS           (S_TILE + KW_ - 1)       // 22
#define THREADS       128
#define XS_ELEMS      (I_PER_BLOCK * BP_PER_BLOCK * POS)  // 2816 = 22*128

#define I_STRIDE      (S_ * KW_)               // 3584 floats
#define W_ROW_F       116                      // padded per-o row; h-stride 464 == 16 mod 32
#define W_WARP_BYTES  (8 * W_ROW_F * 4)        // 3712 B per warp tile
#define W_BUF_BYTES   (4 * W_WARP_BYTES)       // 14848 per buffer (4 warps)
#define XS_BYTES      (XS_ELEMS * 8)           // 22528
#define SMEM_TOTAL    (XS_BYTES + 2 * W_BUF_BYTES)  // 52224

typedef unsigned long long ull;

__device__ __forceinline__ ull pack2(float w) {
    unsigned u = __float_as_uint(w);
    ull r;
    asm("mov.b64 %0, {%1, %1};" : "=l"(r) : "r"(u));
    return r;
}

__device__ __forceinline__ void ffma2(ull &d, ull a, ull b) {
    asm("fma.rn.f32x2 %0, %1, %2, %0;" : "+l"(d) : "l"(a), "l"(b));
}

__device__ __forceinline__ void cp16(unsigned dst, const void* src) {
    asm volatile("cp.async.cg.shared.global [%0], [%1], 16;" :: "r"(dst), "l"(src));
}

__global__ __launch_bounds__(THREADS, 4)
void conv1d_local_kernel(const float* __restrict__ x,
                         const float* __restrict__ w,
                         float* __restrict__ out)
{
    extern __shared__ char smem[];
    // [0, 22528): x tile, float2 xs[(i_l*BP + bp)*POS + pos] = {x[2bp], x[2bp+1]}
    // [22528, 52224): weight tiles [buf][warp][8o x 116f padded rows]
    float2* xs = reinterpret_cast<float2*>(smem);
    char*   ws = smem + XS_BYTES;

    const int tid     = threadIdx.x;
    const int lane    = tid & 31;
    const int warp    = tid >> 5;
    const int s_local = tid & (S_TILE - 1);
    const int og      = tid >> 4;                  // 0..7
    const int h       = og & 1;                    // half within warp
    const int s0      = blockIdx.x * S_TILE;
    const int o_base  = blockIdx.y * 32 + og * O_PER_THREAD;
    const int b_blk   = blockIdx.z & 1;
    const int i_blk   = blockIdx.z >> 1;           // 0..3
    const int b0      = b_blk * (2 * BP_PER_BLOCK);
    const int i0      = i_blk * I_PER_BLOCK;
    const int s       = s0 + s_local;

    // ---- cp.async setup: lane's c-th chunk -> idx = c*32+lane in [0,224)
    // o_idx = idx/28, f4 = idx%28; per o, 112 contiguous floats (28 f4) at
    // w[((o*IC+i)*S + s0)*KW]; smem row padded to 116 floats.
    const unsigned ws_base =
        (unsigned)__cvta_generic_to_shared(ws + warp * W_WARP_BYTES);
    const float* srcp[7];
    unsigned dsto[7];
    #pragma unroll
    for (int c = 0; c < 7; ++c) {
        int idx   = c * 32 + lane;       // 0..223
        int o_idx = idx / 28;
        int f4    = idx - o_idx * 28;
        int o     = blockIdx.y * 32 + warp * 8 + o_idx;
        srcp[c] = w + (((size_t)o * IC_ + i0) * S_ + s0) * KW_ + f4 * 4;
        dsto[c] = (unsigned)(o_idx * (W_ROW_F * 4) + f4 * 16);
    }

    // prefetch weights for i=0 into buf 0
    #pragma unroll
    for (int c = 0; c < 7; ++c)
        cp16(ws_base + dsto[c], srcp[c]);
    asm volatile("cp.async.commit_group;");

    // ---- cooperative x tile load: 16 i x 8 bp x 22 pos
    #pragma unroll
    for (int it = 0; it < XS_ELEMS / THREADS; ++it) {
        int t   = it * THREADS + tid;
        int i_l = t / (BP_PER_BLOCK * POS);
        int r   = t - i_l * (BP_PER_BLOCK * POS);
        int bp  = r / POS;
        int pos = r - bp * POS;
        int b   = b0 + 2 * bp;
        const float* xp = x + ((size_t)b * IC_ + (i0 + i_l)) * L_ + s0 + pos;
        xs[t] = make_float2(xp[0], xp[(size_t)IC_ * L_]);
    }

    ull acc[O_PER_THREAD][BP_PER_BLOCK];
    #pragma unroll
    for (int j = 0; j < O_PER_THREAD; j++)
        #pragma unroll
        for (int bp = 0; bp < BP_PER_BLOCK; bp++)
            acc[j][bp] = 0ull;

    __syncthreads();   // x tile ready

    // consume: thread reads wsf[h*464 + j*116 + s_local*7 + k]
    // banks {7s+k} (h=0) and {7s+k+16} (h=1) disjoint mod 32 -> conflict-free
    const float* wsf0 = reinterpret_cast<const float*>(ws + warp * W_WARP_BYTES);
    const float* wsf1 = reinterpret_cast<const float*>(ws + W_BUF_BYTES + warp * W_WARP_BYTES);
    const int toff = h * (4 * W_ROW_F) + s_local * 7;

    #pragma unroll 2
    for (int i_l = 0; i_l < I_PER_BLOCK; ++i_l) {
        if (i_l + 1 < I_PER_BLOCK) {
            unsigned db = ws_base + (unsigned)(((i_l + 1) & 1) * W_BUF_BYTES);
            #pragma unroll
            for (int c = 0; c < 7; ++c)
                cp16(db + dsto[c], srcp[c] + (size_t)(i_l + 1) * I_STRIDE);
            asm volatile("cp.async.commit_group;");
            asm volatile("cp.async.wait_group 1;");
        } else {
            asm volatile("cp.async.wait_group 0;");
        }
        __syncwarp();

        const float* wsf = (i_l & 1) ? wsf1 : wsf0;
        const float2* xb = xs + i_l * (BP_PER_BLOCK * POS) + s_local;

        #pragma unroll
        for (int k = 0; k < KW_; ++k) {
            ull w2[O_PER_THREAD];
            #pragma unroll
            for (int j = 0; j < O_PER_THREAD; ++j)
                w2[j] = pack2(wsf[toff + j * W_ROW_F + k]);
            #pragma unroll
            for (int bp = 0; bp < BP_PER_BLOCK; ++bp) {
                ull x2 = *reinterpret_cast<const ull*>(&xb[bp * POS + k]);
                #pragma unroll
                for (int j = 0; j < O_PER_THREAD; ++j)
                    ffma2(acc[j][bp], x2, w2[j]);
            }
        }
        __syncwarp();  // all lanes done with buffer before next overwrite
    }

    // accumulate partials (4 i-split blocks per output; out pre-zeroed)
    #pragma unroll
    for (int j = 0; j < O_PER_THREAD; ++j) {
        #pragma unroll
        for (int bp = 0; bp < BP_PER_BLOCK; ++bp) {
            float lo = __uint_as_float((unsigned)(acc[j][bp] & 0xffffffffull));
            float hi = __uint_as_float((unsigned)(acc[j][bp] >> 32));
            int b = b0 + 2 * bp;
            atomicAdd(&out[((size_t)b * OC_ + (o_base + j)) * S_ + s], lo);
            atomicAdd(&out[((size_t)(b + 1) * OC_ + (o_base + j)) * S_ + s], hi);
        }
    }
}

extern "C" void kernel_launch(void* const* d_in, const int* in_sizes, int n_in,
                              void* d_out, int out_size)
{
    const float* x = (const float*)d_in[0];
    const float* w = (const float*)d_in[1];
    float* out = (float*)d_out;

    cudaFuncSetAttribute(conv1d_local_kernel,
                         cudaFuncAttributeMaxDynamicSharedMemorySize, SMEM_TOTAL);

    cudaMemsetAsync(out, 0, (size_t)out_size * sizeof(float), 0);

    dim3 grid(S_ / S_TILE, OC_ / 32,
              (B_ / (2 * BP_PER_BLOCK)) * (IC_ / I_PER_BLOCK)); // 32,2,8
    conv1d_local_kernel<<<grid, THREADS, SMEM_TOTAL>>>(x, w, out);
}